// round 1
// baseline (speedup 1.0000x reference)
#include <cuda_runtime.h>
#include <cstdint>
#include <cstddef>

#define NG   1024
#define DD   512
#define HH   128
#define MAXN 262144

// ---------------- scratch (device globals; no allocation allowed) ----------------
__device__ float    g_logits[MAXN];
__device__ float    g_ex[MAXN];
__device__ unsigned g_segmax[NG];
__device__ float    g_segsum[NG];
__device__ float    g_inv[NG];

// ---------------- helpers ----------------
__device__ __forceinline__ unsigned fenc(float f) {
    unsigned u = __float_as_uint(f);
    return (u & 0x80000000u) ? ~u : (u | 0x80000000u);
}
__device__ __forceinline__ float fdec(unsigned e) {
    return (e & 0x80000000u) ? __uint_as_float(e ^ 0x80000000u)
                             : __uint_as_float(~e);
}

__device__ __forceinline__ unsigned long long pack2(float x) {
    unsigned long long r;
    unsigned xb = __float_as_uint(x);
    asm("mov.b64 %0, {%1, %1};" : "=l"(r) : "r"(xb));
    return r;
}
__device__ __forceinline__ void fma2(unsigned long long& d,
                                     unsigned long long a,
                                     unsigned long long b) {
    // packed f32x2 FMA (FFMA2 in SASS) — 2x scalar FFMA throughput on sm_103a
    asm("fma.rn.f32x2 %0, %1, %2, %0;" : "+l"(d) : "l"(a), "l"(b));
}
__device__ __forceinline__ void unpack2(unsigned long long v, float& lo, float& hi) {
    unsigned a, b;
    asm("mov.b64 {%0, %1}, %2;" : "=r"(a), "=r"(b) : "l"(v));
    lo = __uint_as_float(a);
    hi = __uint_as_float(b);
}

// ---------------- kernel 0: init output + segment scratch ----------------
__global__ void init_kernel(float* __restrict__ out) {
    int i = blockIdx.x * blockDim.x + threadIdx.x;
    if (i < NG * DD) out[i] = 0.0f;
    if (i < NG) {
        g_segmax[i] = 0x007FFFFFu;  // fenc(-inf)
        g_segsum[i] = 0.0f;
    }
}

// ---------------- kernel 1: logits = tanh(h@W1+b1)@W2+b2 ----------------
// Block tile: 128 rows (nodes) x 128 cols (H). K loop over D in steps of 16.
// 256 threads, each computes 8 rows x 8 cols (4 f32x2 column-pairs).
__global__ __launch_bounds__(256, 2)
void logits_kernel(const float* __restrict__ h,
                   const float* __restrict__ W1,
                   const float* __restrict__ b1,
                   const float* __restrict__ W2,
                   const float* __restrict__ b2,
                   int n) {
    __shared__ float As[16][128];   // transposed A tile: As[k][row]
    __shared__ float Bs[16][128];   // B tile: Bs[k][col]
    __shared__ float sb1[HH], sw2[HH];

    const int tid = threadIdx.x;
    const int tx = tid & 15;        // 16 col-groups
    const int ty = tid >> 4;        // 16 row-groups of 8 rows
    const int m0 = blockIdx.x * 128;

    if (tid < HH) { sb1[tid] = b1[tid]; sw2[tid] = W2[tid]; }

    unsigned long long acc[8][4];
#pragma unroll
    for (int i = 0; i < 8; i++)
#pragma unroll
        for (int j = 0; j < 4; j++) acc[i][j] = 0ull;

    for (int k0 = 0; k0 < DD; k0 += 16) {
        // load A tile (128 rows x 16 k), store transposed
#pragma unroll
        for (int q = 0; q < 2; q++) {
            int idx = tid * 2 + q;          // 0..511 float4 slots
            int row = idx >> 2;
            int c4  = idx & 3;
            float4 v = make_float4(0.f, 0.f, 0.f, 0.f);
            if (m0 + row < n)
                v = *reinterpret_cast<const float4*>(
                        h + (size_t)(m0 + row) * DD + k0 + c4 * 4);
            As[c4 * 4 + 0][row] = v.x;
            As[c4 * 4 + 1][row] = v.y;
            As[c4 * 4 + 2][row] = v.z;
            As[c4 * 4 + 3][row] = v.w;
        }
        // load B tile: W1[k0..k0+15][:] is contiguous (2048 floats)
        {
            const float4* src = reinterpret_cast<const float4*>(W1 + (size_t)k0 * HH);
            float4* dst = reinterpret_cast<float4*>(&Bs[0][0]);
            dst[tid * 2]     = src[tid * 2];
            dst[tid * 2 + 1] = src[tid * 2 + 1];
        }
        __syncthreads();

#pragma unroll
        for (int k = 0; k < 16; k++) {
            unsigned long long bb[4];
#pragma unroll
            for (int j = 0; j < 4; j++)
                bb[j] = *reinterpret_cast<const unsigned long long*>(
                            &Bs[k][tx * 2 + 32 * j]);
#pragma unroll
            for (int i = 0; i < 8; i++) {
                unsigned long long aa = pack2(As[k][ty * 8 + i]);
#pragma unroll
                for (int j = 0; j < 4; j++) fma2(acc[i][j], aa, bb[j]);
            }
        }
        __syncthreads();
    }

    // epilogue: tanh, dot with W2, reduce across the 16 col-group lanes
    const float b2v = b2[0];
#pragma unroll
    for (int i = 0; i < 8; i++) {
        float s = 0.0f;
#pragma unroll
        for (int j = 0; j < 4; j++) {
            int c = tx * 2 + 32 * j;
            float x0, x1;
            unpack2(acc[i][j], x0, x1);
            s += tanhf(x0 + sb1[c])     * sw2[c];
            s += tanhf(x1 + sb1[c + 1]) * sw2[c + 1];
        }
#pragma unroll
        for (int sft = 8; sft; sft >>= 1)
            s += __shfl_down_sync(0xffffffffu, s, sft, 16);
        if (tx == 0) {
            int row = m0 + ty * 8 + i;
            if (row < n) g_logits[row] = s + b2v;
        }
    }
}

// ---------------- kernel 2: segment max (warp-aggregated atomics) ----------------
__global__ void segmax_kernel(const int* __restrict__ batch, int n) {
    int i = blockIdx.x * blockDim.x + threadIdx.x;
    if (i >= n) return;
    int g   = batch[i];
    float v = g_logits[i];
    unsigned m = __activemask();
    if (m == 0xffffffffu) {
        int g0 = __shfl_sync(0xffffffffu, g, 0);
        if (__all_sync(0xffffffffu, g == g0)) {
#pragma unroll
            for (int s = 16; s; s >>= 1)
                v = fmaxf(v, __shfl_down_sync(0xffffffffu, v, s));
            if ((threadIdx.x & 31) == 0) atomicMax(&g_segmax[g], fenc(v));
            return;
        }
    }
    atomicMax(&g_segmax[g], fenc(v));
}

// ---------------- kernel 3: ex = exp(logit - max); segment sum ----------------
__global__ void exps_kernel(const int* __restrict__ batch, int n) {
    int i = blockIdx.x * blockDim.x + threadIdx.x;
    if (i >= n) return;
    int g   = batch[i];
    float e = expf(g_logits[i] - fdec(g_segmax[g]));
    g_ex[i] = e;
    unsigned m = __activemask();
    if (m == 0xffffffffu) {
        int g0 = __shfl_sync(0xffffffffu, g, 0);
        if (__all_sync(0xffffffffu, g == g0)) {
            float v = e;
#pragma unroll
            for (int s = 16; s; s >>= 1)
                v += __shfl_down_sync(0xffffffffu, v, s);
            if ((threadIdx.x & 31) == 0) atomicAdd(&g_segsum[g], v);
            return;
        }
    }
    atomicAdd(&g_segsum[g], e);
}

// ---------------- kernel 3b: reciprocal of denom ----------------
__global__ void inv_kernel() {
    int i = blockIdx.x * blockDim.x + threadIdx.x;
    if (i < NG) g_inv[i] = 1.0f / g_segsum[i];
}

// ---------------- kernel 4: pooled[g,:] += h[i,:] * a_i ----------------
// blockIdx.x: chunk of 256 nodes, blockIdx.y: 128-wide d-slice. 128 threads.
__global__ __launch_bounds__(128)
void pool_kernel(const float* __restrict__ h,
                 const int* __restrict__ batch,
                 float* __restrict__ out, int n) {
    int i0 = blockIdx.x * 256;
    if (i0 >= n) return;
    int iend = min(i0 + 256, n);
    int d = blockIdx.y * 128 + threadIdx.x;

    float acc = 0.0f;
    int cur = __ldg(&batch[i0]);
    for (int i = i0; i < iend; i++) {
        int g = __ldg(&batch[i]);
        float w = g_ex[i] * g_inv[g];
        if (g != cur) {
            atomicAdd(&out[(size_t)cur * DD + d], acc);
            acc = 0.0f;
            cur = g;
        }
        acc = fmaf(__ldg(&h[(size_t)i * DD + d]), w, acc);
    }
    atomicAdd(&out[(size_t)cur * DD + d], acc);
}

// ---------------- launch ----------------
extern "C" void kernel_launch(void* const* d_in, const int* in_sizes, int n_in,
                              void* d_out, int out_size) {
    const float* h     = (const float*)d_in[0];
    const int*   batch = (const int*)  d_in[1];
    const float* W1    = (const float*)d_in[2];
    const float* b1    = (const float*)d_in[3];
    const float* W2    = (const float*)d_in[4];
    const float* b2    = (const float*)d_in[5];
    float* out = (float*)d_out;
    const int n = in_sizes[1];  // batch has one entry per node

    init_kernel<<<(NG * DD + 255) / 256, 256>>>(out);
    logits_kernel<<<(n + 127) / 128, 256>>>(h, W1, b1, W2, b2, n);
    segmax_kernel<<<(n + 255) / 256, 256>>>(batch, n);
    exps_kernel<<<(n + 255) / 256, 256>>>(batch, n);
    inv_kernel<<<(NG + 255) / 256, 256>>>();
    dim3 pg((n + 255) / 256, DD / 128);
    pool_kernel<<<pg, 128>>>(h, batch, out, n);
}

// round 8
// speedup vs baseline: 1.9006x; 1.9006x over previous
#include <cuda_runtime.h>
#include <cuda_bf16.h>
#include <cstdint>
#include <cstddef>

#define NG   1024
#define DD   512
#define HH   128
#define MAXN 262144

// ---------------- scratch (device globals; no allocation allowed) ----------------
__device__ float    g_logits[MAXN];
__device__ float    g_ex[MAXN];
__device__ float    g_w[MAXN];
__device__ unsigned g_segmax[NG];
__device__ float    g_segsum[NG];
__device__ float    g_inv[NG];
// W1 pre-transposed + split: [H=128 rows][K=512], K-major, bf16 hi/lo
__device__ __align__(16) __nv_bfloat16 g_Whi[HH * DD];
__device__ __align__(16) __nv_bfloat16 g_Wlo[HH * DD];

// ---------------- helpers ----------------
__device__ __forceinline__ unsigned fenc(float f) {
    unsigned u = __float_as_uint(f);
    return (u & 0x80000000u) ? ~u : (u | 0x80000000u);
}
__device__ __forceinline__ float fdec(unsigned e) {
    return (e & 0x80000000u) ? __uint_as_float(e ^ 0x80000000u)
                             : __uint_as_float(~e);
}

__device__ __forceinline__ void bsplit(float x, unsigned short& hi, unsigned short& lo) {
    __nv_bfloat16 h = __float2bfloat16_rn(x);
    __nv_bfloat16 l = __float2bfloat16_rn(x - __bfloat162float(h));
    hi = *reinterpret_cast<unsigned short*>(&h);
    lo = *reinterpret_cast<unsigned short*>(&l);
}

// mma.sync m16n8k16 row.col bf16 -> f32 (sm_80+ PTX; works on plain sm_103 target)
__device__ __forceinline__ void mma16816(float* c, const unsigned* a, const unsigned* b) {
    asm volatile(
        "mma.sync.aligned.m16n8k16.row.col.f32.bf16.bf16.f32 "
        "{%0,%1,%2,%3}, {%4,%5,%6,%7}, {%8,%9}, {%0,%1,%2,%3};"
        : "+f"(c[0]), "+f"(c[1]), "+f"(c[2]), "+f"(c[3])
        : "r"(a[0]), "r"(a[1]), "r"(a[2]), "r"(a[3]), "r"(b[0]), "r"(b[1]));
}

// ---------------- kernel 0: init output + segment scratch ----------------
__global__ void init_kernel(float* __restrict__ out) {
    int i = blockIdx.x * blockDim.x + threadIdx.x;
    if (i < NG * DD) out[i] = 0.0f;
    if (i < NG) {
        g_segmax[i] = 0x007FFFFFu;  // fenc(-inf)
        g_segsum[i] = 0.0f;
    }
}

// ---------------- kernel 0b: transpose + bf16-split W1 ----------------
// g_Whi[j*512 + k] = hi(W1[k*128 + j]), same for lo.
__global__ void prepW_kernel(const float* __restrict__ W1) {
    int idx = blockIdx.x * blockDim.x + threadIdx.x;
    if (idx >= HH * DD) return;
    int j = idx >> 9;          // H row
    int k = idx & 511;         // K col
    float x = W1[k * HH + j];
    unsigned short hi, lo;
    bsplit(x, hi, lo);
    g_Whi[idx] = *reinterpret_cast<__nv_bfloat16*>(&hi);
    g_Wlo[idx] = *reinterpret_cast<__nv_bfloat16*>(&lo);
}

// ---------------- kernel 1: logits via mma.sync split-bf16 GEMM ----------------
// CTA: M=128 x N=128(H), K=512 in 16 chunks of 32. 8 warps = 4(m) x 2(n).
// Warp tile 32x64. Smem rows padded to 20 words (32 bf16 data + pad) -> no conflicts.
#define KCH     32
#define ROW_W   20                       // words per smem row
#define TILE_W  (128 * ROW_W)            // 2560 words per (matrix, hi/lo)
#define STAGE_W (4 * TILE_W)             // AHI, ALO, BHI, BLO
#define OFF_AHI 0
#define OFF_ALO TILE_W
#define OFF_BHI (2 * TILE_W)
#define OFF_BLO (3 * TILE_W)
#define SMEM_WORDS (2 * STAGE_W)         // double buffer
#define OFF_PART  SMEM_WORDS             // float partial[2][128]
#define OFF_B1    (SMEM_WORDS + 256)
#define OFF_W2    (SMEM_WORDS + 256 + 128)
#define LOGITS_SMEM ((SMEM_WORDS + 256 + 256) * 4)

__global__ __launch_bounds__(256, 2)
void logits_mma_kernel(const float* __restrict__ h,
                       const float* __restrict__ b1,
                       const float* __restrict__ W2,
                       const float* __restrict__ b2,
                       int n) {
    extern __shared__ unsigned sw[];
    float* sf = reinterpret_cast<float*>(sw);

    const int tid = threadIdx.x;
    const int wid = tid >> 5;
    const int lid = tid & 31;
    const int warp_m = wid >> 1;     // 0..3
    const int warp_n = wid & 1;      // 0..1
    const int g8 = lid >> 2;         // 0..7
    const int t4 = lid & 3;          // 0..3
    const int m0 = blockIdx.x * 128;

    if (tid < HH) {
        sf[OFF_B1 + tid] = b1[tid];
        sf[OFF_W2 + tid] = W2[tid];
    }

    float acc[2][8][4];
#pragma unroll
    for (int i = 0; i < 2; i++)
#pragma unroll
        for (int j = 0; j < 8; j++)
#pragma unroll
            for (int q = 0; q < 4; q++) acc[i][j][q] = 0.0f;

    // ---- chunk loader ----
    auto load_chunk = [&](int c) {
        unsigned* stg = sw + (c & 1) * STAGE_W;
        const int k0 = c * KCH;
        // A: 128 rows x 32 k fp32 -> bf16 hi/lo. 1024 float4 slots, 4/thread.
#pragma unroll
        for (int q = 0; q < 4; q++) {
            int slot = q * 256 + tid;
            int row = slot >> 3;
            int c4  = slot & 7;           // float4 index within 32-k row
            float4 v = make_float4(0.f, 0.f, 0.f, 0.f);
            int m = m0 + row;
            if (m < n)
                v = *reinterpret_cast<const float4*>(
                        h + (size_t)m * DD + k0 + c4 * 4);
            unsigned short h0, h1, h2, h3, l0, l1, l2, l3;
            bsplit(v.x, h0, l0); bsplit(v.y, h1, l1);
            bsplit(v.z, h2, l2); bsplit(v.w, h3, l3);
            uint2 hp = make_uint2((unsigned)h0 | ((unsigned)h1 << 16),
                                  (unsigned)h2 | ((unsigned)h3 << 16));
            uint2 lp = make_uint2((unsigned)l0 | ((unsigned)l1 << 16),
                                  (unsigned)l2 | ((unsigned)l3 << 16));
            int wa = row * ROW_W + c4 * 2;
            *reinterpret_cast<uint2*>(stg + OFF_AHI + wa) = hp;
            *reinterpret_cast<uint2*>(stg + OFF_ALO + wa) = lp;
        }
        // B: 128 n-rows x 32 k bf16 hi/lo from prepped W1. 512 uint4 slots, 2/thread.
#pragma unroll
        for (int q = 0; q < 2; q++) {
            int slot = q * 256 + tid;
            int row = slot >> 2;
            int c16 = slot & 3;           // 16B unit (8 bf16)
            uint4 vh = *reinterpret_cast<const uint4*>(g_Whi + row * DD + k0 + c16 * 8);
            uint4 vl = *reinterpret_cast<const uint4*>(g_Wlo + row * DD + k0 + c16 * 8);
            int wa = row * ROW_W + c16 * 4;
            *reinterpret_cast<uint4*>(stg + OFF_BHI + wa) = vh;
            *reinterpret_cast<uint4*>(stg + OFF_BLO + wa) = vl;
        }
    };

    load_chunk(0);
    __syncthreads();

    for (int c = 0; c < 16; c++) {
        if (c + 1 < 16) load_chunk(c + 1);

        unsigned* stg = sw + (c & 1) * STAGE_W;
#pragma unroll
        for (int ks = 0; ks < 2; ks++) {
            const int kk = ks * 16;        // k offset within chunk (bf16 units)
            const int kw = (kk + 2 * t4) >> 1;  // word offset of this thread's k pair
            // A fragments for both m-tiles, hi & lo
            unsigned ah[2][4], al[2][4];
#pragma unroll
            for (int i = 0; i < 2; i++) {
                int r0 = warp_m * 32 + i * 16 + g8;
                int w00 = r0 * ROW_W + kw;
                int w10 = (r0 + 8) * ROW_W + kw;
                ah[i][0] = stg[OFF_AHI + w00];
                ah[i][1] = stg[OFF_AHI + w10];
                ah[i][2] = stg[OFF_AHI + w00 + 4];
                ah[i][3] = stg[OFF_AHI + w10 + 4];
                al[i][0] = stg[OFF_ALO + w00];
                al[i][1] = stg[OFF_ALO + w10];
                al[i][2] = stg[OFF_ALO + w00 + 4];
                al[i][3] = stg[OFF_ALO + w10 + 4];
            }
#pragma unroll
            for (int j = 0; j < 8; j++) {
                int nn = warp_n * 64 + j * 8 + g8;
                int wb = nn * ROW_W + kw;
                unsigned bh[2], bl[2];
                bh[0] = stg[OFF_BHI + wb];
                bh[1] = stg[OFF_BHI + wb + 4];
                bl[0] = stg[OFF_BLO + wb];
                bl[1] = stg[OFF_BLO + wb + 4];
#pragma unroll
                for (int i = 0; i < 2; i++) {
                    mma16816(acc[i][j], ah[i], bh);   // hi * hi
                    mma16816(acc[i][j], ah[i], bl);   // hi * lo
                    mma16816(acc[i][j], al[i], bh);   // lo * hi
                }
            }
        }
        __syncthreads();
    }

    // ---- epilogue: tanh + dot(W2), reduce to per-row logit ----
    // c0:(m=g8, n=2t4), c1:(m=g8, n=2t4+1), c2:(m=g8+8, n=2t4), c3:(m=g8+8, n=2t4+1)
#pragma unroll
    for (int i = 0; i < 2; i++) {
        float s0 = 0.0f, s1 = 0.0f;
#pragma unroll
        for (int j = 0; j < 8; j++) {
            int cA = warp_n * 64 + j * 8 + 2 * t4;
            float bA = sf[OFF_B1 + cA],     wA = sf[OFF_W2 + cA];
            float bB = sf[OFF_B1 + cA + 1], wB = sf[OFF_W2 + cA + 1];
            s0 += tanhf(acc[i][j][0] + bA) * wA + tanhf(acc[i][j][1] + bB) * wB;
            s1 += tanhf(acc[i][j][2] + bA) * wA + tanhf(acc[i][j][3] + bB) * wB;
        }
        s0 += __shfl_xor_sync(0xffffffffu, s0, 1);
        s0 += __shfl_xor_sync(0xffffffffu, s0, 2);
        s1 += __shfl_xor_sync(0xffffffffu, s1, 1);
        s1 += __shfl_xor_sync(0xffffffffu, s1, 2);
        if (t4 == 0) {
            int r0 = warp_m * 32 + i * 16 + g8;
            sf[OFF_PART + warp_n * 128 + r0] = s0;
            sf[OFF_PART + warp_n * 128 + r0 + 8] = s1;
        }
    }
    __syncthreads();

    if (tid < 128) {
        int row = m0 + tid;
        if (row < n)
            g_logits[row] = __ldg(b2) + sf[OFF_PART + tid] + sf[OFF_PART + 128 + tid];
    }
}

// ---------------- kernel 2: segment max (warp-aggregated atomics) ----------------
__global__ void segmax_kernel(const int* __restrict__ batch, int n) {
    int i = blockIdx.x * blockDim.x + threadIdx.x;
    if (i >= n) return;
    int g   = batch[i];
    float v = g_logits[i];
    unsigned m = __activemask();
    if (m == 0xffffffffu) {
        int g0 = __shfl_sync(0xffffffffu, g, 0);
        if (__all_sync(0xffffffffu, g == g0)) {
#pragma unroll
            for (int s = 16; s; s >>= 1)
                v = fmaxf(v, __shfl_down_sync(0xffffffffu, v, s));
            if ((threadIdx.x & 31) == 0) atomicMax(&g_segmax[g], fenc(v));
            return;
        }
    }
    atomicMax(&g_segmax[g], fenc(v));
}

// ---------------- kernel 3: ex = exp(logit - max); segment sum ----------------
__global__ void exps_kernel(const int* __restrict__ batch, int n) {
    int i = blockIdx.x * blockDim.x + threadIdx.x;
    if (i >= n) return;
    int g   = batch[i];
    float e = expf(g_logits[i] - fdec(g_segmax[g]));
    g_ex[i] = e;
    unsigned m = __activemask();
    if (m == 0xffffffffu) {
        int g0 = __shfl_sync(0xffffffffu, g, 0);
        if (__all_sync(0xffffffffu, g == g0)) {
            float v = e;
#pragma unroll
            for (int s = 16; s; s >>= 1)
                v += __shfl_down_sync(0xffffffffu, v, s);
            if ((threadIdx.x & 31) == 0) atomicAdd(&g_segsum[g], v);
            return;
        }
    }
    atomicAdd(&g_segsum[g], e);
}

// ---------------- kernel 3b: reciprocal of denom ----------------
__global__ void inv_kernel() {
    int i = blockIdx.x * blockDim.x + threadIdx.x;
    if (i < NG) g_inv[i] = 1.0f / g_segsum[i];
}

// ---------------- kernel 3c: per-node softmax weight ----------------
__global__ void weights_kernel(const int* __restrict__ batch, int n) {
    int i = blockIdx.x * blockDim.x + threadIdx.x;
    if (i < n) g_w[i] = g_ex[i] * g_inv[batch[i]];
}

// ---------------- kernel 4: pooled[g,:] += h[i,:] * w_i (float2) ----------------
__global__ __launch_bounds__(128)
void pool_kernel(const float* __restrict__ h,
                 const int* __restrict__ batch,
                 float* __restrict__ out, int n) {
    int i0 = blockIdx.x * 256;
    if (i0 >= n) return;
    int iend = min(i0 + 256, n);
    int d = (blockIdx.y * 128 + threadIdx.x) * 2;

    float2 acc = make_float2(0.0f, 0.0f);
    int cur = __ldg(&batch[i0]);
    for (int i = i0; i < iend; i++) {
        int g = __ldg(&batch[i]);
        float w = g_w[i];
        if (g != cur) {
            atomicAdd(&out[(size_t)cur * DD + d],     acc.x);
            atomicAdd(&out[(size_t)cur * DD + d + 1], acc.y);
            acc = make_float2(0.0f, 0.0f);
            cur = g;
        }
        float2 hv = *reinterpret_cast<const float2*>(h + (size_t)i * DD + d);
        acc.x = fmaf(hv.x, w, acc.x);
        acc.y = fmaf(hv.y, w, acc.y);
    }
    atomicAdd(&out[(size_t)cur * DD + d],     acc.x);
    atomicAdd(&out[(size_t)cur * DD + d + 1], acc.y);
}

// ---------------- launch ----------------
extern "C" void kernel_launch(void* const* d_in, const int* in_sizes, int n_in,
                              void* d_out, int out_size) {
    const float* h     = (const float*)d_in[0];
    const int*   batch = (const int*)  d_in[1];
    const float* W1    = (const float*)d_in[2];
    const float* b1    = (const float*)d_in[3];
    const float* W2    = (const float*)d_in[4];
    const float* b2    = (const float*)d_in[5];
    float* out = (float*)d_out;
    const int n = in_sizes[1];  // batch has one entry per node

    cudaFuncSetAttribute(logits_mma_kernel,
                         cudaFuncAttributeMaxDynamicSharedMemorySize, LOGITS_SMEM);

    init_kernel<<<(NG * DD + 255) / 256, 256>>>(out);
    prepW_kernel<<<(HH * DD + 255) / 256, 256>>>(W1);
    logits_mma_kernel<<<(n + 127) / 128, 256, LOGITS_SMEM>>>(h, b1, W2, b2, n);
    segmax_kernel<<<(n + 255) / 256, 256>>>(batch, n);
    exps_kernel<<<(n + 255) / 256, 256>>>(batch, n);
    inv_kernel<<<(NG + 255) / 256, 256>>>();
    weights_kernel<<<(n + 255) / 256, 256>>>(batch, n);
    dim3 pg((n + 255) / 256, DD / 256);
    pool_kernel<<<pg, 128>>>(h, batch, out, n);
}

// round 15
// speedup vs baseline: 2.1114x; 1.1109x over previous
#include <cuda_runtime.h>
#include <cuda_bf16.h>
#include <cstdint>
#include <cstddef>

#define NG   1024
#define DD   512
#define HH   128
#define MAXN 262144

// ---------------- scratch (device globals; no allocation allowed) ----------------
__device__ float g_logits[MAXN];
// W1 pre-transposed + split: [H=128 rows][K=512], K-major, bf16 hi/lo
__device__ __align__(16) __nv_bfloat16 g_Whi[HH * DD];
__device__ __align__(16) __nv_bfloat16 g_Wlo[HH * DD];

// ---------------- helpers ----------------
__device__ __forceinline__ void bsplit(float x, unsigned short& hi, unsigned short& lo) {
    __nv_bfloat16 h = __float2bfloat16_rn(x);
    __nv_bfloat16 l = __float2bfloat16_rn(x - __bfloat162float(h));
    hi = *reinterpret_cast<unsigned short*>(&h);
    lo = *reinterpret_cast<unsigned short*>(&l);
}

__device__ __forceinline__ uint32_t smem_u32(const void* p) {
    uint32_t a;
    asm("{ .reg .u64 t; cvta.to.shared.u64 t, %1; cvt.u32.u64 %0, t; }"
        : "=r"(a) : "l"(p));
    return a;
}

__device__ __forceinline__ void cpasync16(uint32_t saddr, const void* gaddr) {
    asm volatile("cp.async.ca.shared.global [%0], [%1], 16;"
                 :: "r"(saddr), "l"(gaddr) : "memory");
}

// mma.sync m16n8k16 row.col bf16 -> f32 (sm_80+ PTX; works on plain sm_103 target)
__device__ __forceinline__ void mma16816(float* c, const unsigned* a, const unsigned* b) {
    asm volatile(
        "mma.sync.aligned.m16n8k16.row.col.f32.bf16.bf16.f32 "
        "{%0,%1,%2,%3}, {%4,%5,%6,%7}, {%8,%9}, {%0,%1,%2,%3};"
        : "+f"(c[0]), "+f"(c[1]), "+f"(c[2]), "+f"(c[3])
        : "r"(a[0]), "r"(a[1]), "r"(a[2]), "r"(a[3]), "r"(b[0]), "r"(b[1]));
}

// ---------------- kernel 0b: transpose + bf16-split W1 ----------------
// g_Whi[j*512 + k] = hi(W1[k*128 + j]), same for lo.
__global__ void prepW_kernel(const float* __restrict__ W1) {
    int idx = blockIdx.x * blockDim.x + threadIdx.x;
    if (idx >= HH * DD) return;
    int j = idx >> 9;          // H row
    int k = idx & 511;         // K col
    float x = W1[k * HH + j];
    unsigned short hi, lo;
    bsplit(x, hi, lo);
    g_Whi[idx] = *reinterpret_cast<__nv_bfloat16*>(&hi);
    g_Wlo[idx] = *reinterpret_cast<__nv_bfloat16*>(&lo);
}

// ---------------- kernel 1: logits via mma.sync split-bf16 GEMM ----------------
// CTA: M=128 x N=128(H), K=512 in 16 chunks of 32. 8 warps = 4(m) x 2(n).
// Warp tile 32x64. Smem rows padded to 20 words -> no bank conflicts.
// Software-pipelined: A LDGs for chunk c+1 issued into registers before the
// MMAs on chunk c (convert+STS after); B tiles via cp.async (no convert needed).
#define KCH     32
#define ROW_W   20                       // words per smem row
#define TILE_W  (128 * ROW_W)            // 2560 words per (matrix, hi/lo)
#define STAGE_W (4 * TILE_W)             // AHI, ALO, BHI, BLO
#define OFF_AHI 0
#define OFF_ALO TILE_W
#define OFF_BHI (2 * TILE_W)
#define OFF_BLO (3 * TILE_W)
#define SMEM_WORDS (2 * STAGE_W)         // double buffer
#define OFF_PART  SMEM_WORDS             // float partial[2][128]
#define OFF_B1    (SMEM_WORDS + 256)
#define OFF_W2    (SMEM_WORDS + 256 + 128)
#define LOGITS_SMEM ((SMEM_WORDS + 256 + 256) * 4)

__global__ __launch_bounds__(256, 2)
void logits_mma_kernel(const float* __restrict__ h,
                       const float* __restrict__ b1,
                       const float* __restrict__ W2,
                       const float* __restrict__ b2,
                       int n) {
    extern __shared__ unsigned sw[];
    float* sf = reinterpret_cast<float*>(sw);
    const uint32_t sbase = smem_u32(sw);

    const int tid = threadIdx.x;
    const int wid = tid >> 5;
    const int lid = tid & 31;
    const int warp_m = wid >> 1;     // 0..3
    const int warp_n = wid & 1;      // 0..1
    const int g8 = lid >> 2;         // 0..7
    const int t4 = lid & 3;          // 0..3
    const int m0 = blockIdx.x * 128;

    if (tid < HH) {
        sf[OFF_B1 + tid] = b1[tid];
        sf[OFF_W2 + tid] = W2[tid];
    }

    float acc[2][8][4];
#pragma unroll
    for (int i = 0; i < 2; i++)
#pragma unroll
        for (int j = 0; j < 8; j++)
#pragma unroll
            for (int q = 0; q < 4; q++) acc[i][j][q] = 0.0f;

    float4 av[4];   // A staging registers (chunk in flight)

    // issue A LDGs for chunk c into av[] (no stall until store_A uses them)
    auto issue_A = [&](int c) {
        const int k0 = c * KCH;
#pragma unroll
        for (int q = 0; q < 4; q++) {
            int slot = q * 256 + tid;
            int row = slot >> 3;
            int c4  = slot & 7;
            int m = m0 + row;
            av[q] = make_float4(0.f, 0.f, 0.f, 0.f);
            if (m < n)
                av[q] = *reinterpret_cast<const float4*>(
                            h + (size_t)m * DD + k0 + c4 * 4);
        }
    };
    // convert av[] -> bf16 hi/lo, store to stage (c&1)
    auto store_A = [&](int c) {
        unsigned* stg = sw + (c & 1) * STAGE_W;
#pragma unroll
        for (int q = 0; q < 4; q++) {
            int slot = q * 256 + tid;
            int row = slot >> 3;
            int c4  = slot & 7;
            unsigned short h0, h1, h2, h3, l0, l1, l2, l3;
            bsplit(av[q].x, h0, l0); bsplit(av[q].y, h1, l1);
            bsplit(av[q].z, h2, l2); bsplit(av[q].w, h3, l3);
            uint2 hp = make_uint2((unsigned)h0 | ((unsigned)h1 << 16),
                                  (unsigned)h2 | ((unsigned)h3 << 16));
            uint2 lp = make_uint2((unsigned)l0 | ((unsigned)l1 << 16),
                                  (unsigned)l2 | ((unsigned)l3 << 16));
            int wa = row * ROW_W + c4 * 2;
            *reinterpret_cast<uint2*>(stg + OFF_AHI + wa) = hp;
            *reinterpret_cast<uint2*>(stg + OFF_ALO + wa) = lp;
        }
    };
    // B tiles: cp.async 16B straight global->smem (bf16 already prepped)
    auto issue_B = [&](int c) {
        const int k0 = c * KCH;
        const uint32_t sb = sbase + ((c & 1) * STAGE_W) * 4u;
#pragma unroll
        for (int q = 0; q < 2; q++) {
            int slot = q * 256 + tid;
            int row = slot >> 2;
            int c16 = slot & 3;
            uint32_t wa = (uint32_t)(row * ROW_W + c16 * 4) * 4u;
            cpasync16(sb + OFF_BHI * 4u + wa, g_Whi + row * DD + k0 + c16 * 8);
            cpasync16(sb + OFF_BLO * 4u + wa, g_Wlo + row * DD + k0 + c16 * 8);
        }
        asm volatile("cp.async.commit_group;" ::: "memory");
    };

    // prologue: chunk 0
    issue_A(0);
    issue_B(0);
    store_A(0);
    asm volatile("cp.async.wait_group 0;" ::: "memory");
    __syncthreads();

    for (int c = 0; c < 16; c++) {
        if (c + 1 < 16) {
            issue_A(c + 1);      // LDGs in flight across the MMA block
            issue_B(c + 1);      // cp.async in flight
        }

        unsigned* stg = sw + (c & 1) * STAGE_W;
#pragma unroll
        for (int ks = 0; ks < 2; ks++) {
            const int kk = ks * 16;
            const int kw = (kk + 2 * t4) >> 1;
            unsigned ah[2][4], al[2][4];
#pragma unroll
            for (int i = 0; i < 2; i++) {
                int r0 = warp_m * 32 + i * 16 + g8;
                int w00 = r0 * ROW_W + kw;
                int w10 = (r0 + 8) * ROW_W + kw;
                ah[i][0] = stg[OFF_AHI + w00];
                ah[i][1] = stg[OFF_AHI + w10];
                ah[i][2] = stg[OFF_AHI + w00 + 4];
                ah[i][3] = stg[OFF_AHI + w10 + 4];
                al[i][0] = stg[OFF_ALO + w00];
                al[i][1] = stg[OFF_ALO + w10];
                al[i][2] = stg[OFF_ALO + w00 + 4];
                al[i][3] = stg[OFF_ALO + w10 + 4];
            }
#pragma unroll
            for (int j = 0; j < 8; j++) {
                int nn = warp_n * 64 + j * 8 + g8;
                int wb = nn * ROW_W + kw;
                unsigned bh[2], bl[2];
                bh[0] = stg[OFF_BHI + wb];
                bh[1] = stg[OFF_BHI + wb + 4];
                bl[0] = stg[OFF_BLO + wb];
                bl[1] = stg[OFF_BLO + wb + 4];
#pragma unroll
                for (int i = 0; i < 2; i++) {
                    mma16816(acc[i][j], ah[i], bh);   // hi * hi
                    mma16816(acc[i][j], ah[i], bl);   // hi * lo
                    mma16816(acc[i][j], al[i], bh);   // lo * hi
                }
            }
        }

        if (c + 1 < 16) {
            store_A(c + 1);      // convert now that LDGs have landed
            asm volatile("cp.async.wait_group 0;" ::: "memory");
        }
        __syncthreads();
    }

    // ---- epilogue: tanh + dot(W2), reduce to per-row logit ----
#pragma unroll
    for (int i = 0; i < 2; i++) {
        float s0 = 0.0f, s1 = 0.0f;
#pragma unroll
        for (int j = 0; j < 8; j++) {
            int cA = warp_n * 64 + j * 8 + 2 * t4;
            float bA = sf[OFF_B1 + cA],     wA = sf[OFF_W2 + cA];
            float bB = sf[OFF_B1 + cA + 1], wB = sf[OFF_W2 + cA + 1];
            s0 += tanhf(acc[i][j][0] + bA) * wA + tanhf(acc[i][j][1] + bB) * wB;
            s1 += tanhf(acc[i][j][2] + bA) * wA + tanhf(acc[i][j][3] + bB) * wB;
        }
        s0 += __shfl_xor_sync(0xffffffffu, s0, 1);
        s0 += __shfl_xor_sync(0xffffffffu, s0, 2);
        s1 += __shfl_xor_sync(0xffffffffu, s1, 1);
        s1 += __shfl_xor_sync(0xffffffffu, s1, 2);
        if (t4 == 0) {
            int r0 = warp_m * 32 + i * 16 + g8;
            sf[OFF_PART + warp_n * 128 + r0] = s0;
            sf[OFF_PART + warp_n * 128 + r0 + 8] = s1;
        }
    }
    __syncthreads();

    if (tid < 128) {
        int row = m0 + tid;
        if (row < n)
            g_logits[row] = __ldg(b2) + sf[OFF_PART + tid] + sf[OFF_PART + 128 + tid];
    }
}

// ---------------- kernel 2: fused segment softmax + weighted pooling ----------------
// One CTA per graph. batch is sorted -> binary search [lo, hi). Block-reduce
// max and sum(exp), stage weights in smem tiles, stream h rows once, write
// out[g,:] exactly once. No atomics, no scratch arrays, no output pre-zeroing.
#define WTILE 2048

__global__ __launch_bounds__(256)
void graph_pool_kernel(const float* __restrict__ h,
                       const int* __restrict__ batch,
                       float* __restrict__ out, int n) {
    __shared__ int   sbounds[2];
    __shared__ float sred[8];
    __shared__ float swt[WTILE];

    const int tid = threadIdx.x;
    const int wid = tid >> 5;
    const int lid = tid & 31;
    const int g = blockIdx.x;

    // binary search graph boundaries in sorted batch
    if (tid < 2) {
        int key = g + tid;          // lower_bound(key)
        int lo = 0, hi = n;
        while (lo < hi) {
            int mid = (lo + hi) >> 1;
            if (__ldg(&batch[mid]) < key) lo = mid + 1;
            else hi = mid;
        }
        sbounds[tid] = lo;
    }
    __syncthreads();
    const int lo = sbounds[0], hi = sbounds[1];

    // ---- block max of logits[lo..hi) ----
    float m = -3.402823466e38f;
    for (int i = lo + tid; i < hi; i += 256)
        m = fmaxf(m, g_logits[i]);
#pragma unroll
    for (int s = 16; s; s >>= 1)
        m = fmaxf(m, __shfl_xor_sync(0xffffffffu, m, s));
    if (lid == 0) sred[wid] = m;
    __syncthreads();
    m = sred[lid & 7];
#pragma unroll
    for (int s = 4; s; s >>= 1)
        m = fmaxf(m, __shfl_xor_sync(0xffffffffu, m, s));
    m = __shfl_sync(0xffffffffu, m, 0);
    __syncthreads();

    // ---- block sum of exp(logit - m) ----
    float ssum = 0.0f;
    for (int i = lo + tid; i < hi; i += 256)
        ssum += expf(g_logits[i] - m);
#pragma unroll
    for (int s = 16; s; s >>= 1)
        ssum += __shfl_xor_sync(0xffffffffu, ssum, s);
    if (lid == 0) sred[wid] = ssum;
    __syncthreads();
    ssum = sred[lid & 7];
#pragma unroll
    for (int s = 4; s; s >>= 1)
        ssum += __shfl_xor_sync(0xffffffffu, ssum, s);
    ssum = __shfl_sync(0xffffffffu, ssum, 0);
    const float inv = 1.0f / ssum;
    __syncthreads();

    // ---- weighted pooling: acc over this CTA's 2 d-columns per thread ----
    const int d = tid * 2;
    float ax = 0.0f, ay = 0.0f;

    for (int t0 = lo; t0 < hi; t0 += WTILE) {
        const int tcnt = min(WTILE, hi - t0);
        for (int i = tid; i < tcnt; i += 256)
            swt[i] = expf(g_logits[t0 + i] - m) * inv;
        __syncthreads();

        int r = 0;
        const float* hp = h + (size_t)t0 * DD + d;
#pragma unroll 4
        for (; r < tcnt; r++) {
            float w = swt[r];
            float2 hv = *reinterpret_cast<const float2*>(hp);
            ax = fmaf(hv.x, w, ax);
            ay = fmaf(hv.y, w, ay);
            hp += DD;
        }
        __syncthreads();
    }

    out[(size_t)g * DD + d]     = ax;
    out[(size_t)g * DD + d + 1] = ay;
}

// ---------------- launch ----------------
extern "C" void kernel_launch(void* const* d_in, const int* in_sizes, int n_in,
                              void* d_out, int out_size) {
    const float* h     = (const float*)d_in[0];
    const int*   batch = (const int*)  d_in[1];
    const float* W1    = (const float*)d_in[2];
    const float* b1    = (const float*)d_in[3];
    const float* W2    = (const float*)d_in[4];
    const float* b2    = (const float*)d_in[5];
    float* out = (float*)d_out;
    const int n = in_sizes[1];  // batch has one entry per node

    cudaFuncSetAttribute(logits_mma_kernel,
                         cudaFuncAttributeMaxDynamicSharedMemorySize, LOGITS_SMEM);

    prepW_kernel<<<(HH * DD + 255) / 256, 256>>>(W1);
    logits_mma_kernel<<<(n + 127) / 128, 256, LOGITS_SMEM>>>(h, b1, W2, b2, n);
    graph_pool_kernel<<<NG, 256>>>(h, batch, out, n);
}